// round 12
// baseline (speedup 1.0000x reference)
#include <cuda_runtime.h>
#include <math.h>

// Self-convolution via real-packed shared-memory FFT: radix-8 fused passes,
// NT=512, packed f32x2 butterflies, scoped sync, table-free twiddles,
// zero-pad-aware pass1 (inputs straight from gmem), register-fused center
// with ALGEBRAICALLY REDUCED middle:
//   E' = 0.5*hm*(e^2 + W^2 * o^2),  O' = hm * e*o   (twiddle cancels in O'),
//   W^2 = W_M^{k_base} * E8^{brev3(r)}  -> 1 sincosf per center thread.

#define SEQ_L   4096
#define OUT_L   (2 * SEQ_L - 1)     // 8191
#define FFT_M   4096
#define NT      512

#define IDX(a)  ((a) + (((a) >> 4) << 1))       // pad 2 slots per 16 (best measured)
#define RE_SZ   (FFT_M + ((FFT_M >> 4) << 1))   // 4608 complex slots (36 KB)
#define S8      0.70710678118654752440f
#define C16     0.92387953251128675613f
#define S16     0.38268343236508977173f
#define W_ANG   (-6.28318530717958647692f / (float)FFT_M)

#define BAR_PAIR(tid) asm volatile("bar.sync %0, 64;" :: "r"(1 + ((tid) >> 6)) : "memory")

typedef unsigned long long q64;   // packed (float lo, float hi) complex

// ---------- packed f32x2 primitives ----------
__device__ __forceinline__ q64 qpk(float x, float y) {
    q64 r; asm("mov.b64 %0,{%1,%2};" : "=l"(r) : "f"(x), "f"(y)); return r;
}
__device__ __forceinline__ float2 qun(q64 a) {
    float2 f; asm("mov.b64 {%0,%1},%2;" : "=f"(f.x), "=f"(f.y) : "l"(a)); return f;
}
__device__ __forceinline__ q64 qswp(q64 a) {
    q64 r;
    asm("{\n\t.reg .b32 lo,hi;\n\tmov.b64 {lo,hi},%1;\n\tmov.b64 %0,{hi,lo};\n\t}"
        : "=l"(r) : "l"(a));
    return r;
}
__device__ __forceinline__ q64 qadd(q64 a, q64 b) {
    q64 r; asm("add.rn.f32x2 %0,%1,%2;" : "=l"(r) : "l"(a), "l"(b)); return r;
}
__device__ __forceinline__ q64 qmul(q64 a, q64 b) {
    q64 r; asm("mul.rn.f32x2 %0,%1,%2;" : "=l"(r) : "l"(a), "l"(b)); return r;
}
__device__ __forceinline__ q64 qfma(q64 a, q64 b, q64 c) {
    q64 r; asm("fma.rn.f32x2 %0,%1,%2,%3;" : "=l"(r) : "l"(a), "l"(b), "l"(c)); return r;
}
__device__ __forceinline__ q64 qsub(q64 a, q64 b, q64 n1) { return qfma(b, n1, a); }

struct qtw { q64 xx, sy; };
__device__ __forceinline__ qtw mk(float p, float q) {
    qtw t; t.xx = qpk(p, p); t.sy = qpk(-q, q); return t;
}
__device__ __forceinline__ q64 qcmul(q64 a, qtw t) {
    return qfma(qswp(a), t.sy, qmul(a, t.xx));
}

// ---------- scalar complex ----------
__device__ __forceinline__ float2 cmul(float2 a, float2 w) {
    return make_float2(a.x * w.x - a.y * w.y, a.x * w.y + a.y * w.x);
}
__device__ __forceinline__ float2 cmulj(float2 a, float2 w) {
    return make_float2(a.x * w.x + a.y * w.y, a.y * w.x - a.x * w.y);
}
__device__ __forceinline__ float2 cadd(float2 a, float2 b) {
    return make_float2(a.x + b.x, a.y + b.y);
}
__device__ __forceinline__ float2 csub(float2 a, float2 b) {
    return make_float2(a.x - b.x, a.y - b.y);
}
__device__ __forceinline__ float2 csq(float2 a) {   // a^2 (complex)
    return make_float2(a.x * a.x - a.y * a.y, 2.0f * a.x * a.y);
}
__device__ __forceinline__ float2 twof(int t) {     // exp(i * W_ANG * t)
    float2 w;
    __sincosf(W_ANG * (float)t, &w.y, &w.x);
    return w;
}

extern __shared__ q64 s_z[];

// ---------- packed radix-8 ----------
__device__ __forceinline__ void qfwd8_s23(q64 v[8], float2 w2, float2 w4, q64 n1) {
    const qtw T2  = mk(w2.x, w2.y);
    const qtw T2N = mk(w2.y, -w2.x);
    #pragma unroll
    for (int h = 0; h < 8; h += 4) {
        q64 u = qsub(v[h + 0], v[h + 2], n1);
        v[h + 0] = qadd(v[h + 0], v[h + 2]);
        v[h + 2] = qcmul(u, T2);
        u = qsub(v[h + 1], v[h + 3], n1);
        v[h + 1] = qadd(v[h + 1], v[h + 3]);
        v[h + 3] = qcmul(u, T2N);
    }
    const qtw T4 = mk(w4.x, w4.y);
    #pragma unroll
    for (int h = 0; h < 8; h += 2) {
        const q64 u = qsub(v[h], v[h + 1], n1);
        v[h] = qadd(v[h], v[h + 1]);
        v[h + 1] = qcmul(u, T4);
    }
}

__device__ __forceinline__ void qfwd8(q64 v[8], float2 w1, float2 w2, float2 w4, q64 n1) {
    const qtw T1 = mk(w1.x, w1.y);
    const qtw TB = mk(S8 * (w1.x + w1.y), S8 * (w1.y - w1.x));
    const qtw TC = mk(w1.y, -w1.x);
    const qtw TD = mk(-S8 * (w1.x - w1.y), -S8 * (w1.y + w1.x));

    q64 d0 = qsub(v[0], v[4], n1), d1 = qsub(v[1], v[5], n1);
    q64 d2 = qsub(v[2], v[6], n1), d3 = qsub(v[3], v[7], n1);
    v[0] = qadd(v[0], v[4]);
    v[1] = qadd(v[1], v[5]);
    v[2] = qadd(v[2], v[6]);
    v[3] = qadd(v[3], v[7]);
    v[4] = qcmul(d0, T1);
    v[5] = qcmul(d1, TB);
    v[6] = qcmul(d2, TC);
    v[7] = qcmul(d3, TD);

    qfwd8_s23(v, w2, w4, n1);
}

__device__ __forceinline__ void qinv8(q64 v[8], float2 w1, float2 w2, float2 w4, q64 n1) {
    const qtw T4C = mk(w4.x, -w4.y);
    #pragma unroll
    for (int h = 0; h < 8; h += 2) {
        const q64 t = qcmul(v[h + 1], T4C);
        v[h + 1] = qsub(v[h], t, n1);
        v[h]     = qadd(v[h], t);
    }
    const qtw T2C = mk(w2.x, -w2.y);
    const qtw T2I = mk(w2.y, w2.x);
    #pragma unroll
    for (int h = 0; h < 8; h += 4) {
        q64 t = qcmul(v[h + 2], T2C);
        v[h + 2] = qsub(v[h], t, n1);
        v[h]     = qadd(v[h], t);
        t = qcmul(v[h + 3], T2I);
        v[h + 3] = qsub(v[h + 1], t, n1);
        v[h + 1] = qadd(v[h + 1], t);
    }
    {
        const qtw T1C = mk(w1.x, -w1.y);
        const qtw TC1 = mk(S8 * (w1.x + w1.y), S8 * (w1.x - w1.y));
        const qtw TC2 = mk(w1.y, w1.x);
        const qtw TC3 = mk(-S8 * (w1.x - w1.y), S8 * (w1.y + w1.x));

        q64 t = qcmul(v[4], T1C);
        v[4] = qsub(v[0], t, n1);
        v[0] = qadd(v[0], t);
        t = qcmul(v[5], TC1);
        v[5] = qsub(v[1], t, n1);
        v[1] = qadd(v[1], t);
        t = qcmul(v[6], TC2);
        v[6] = qsub(v[2], t, n1);
        v[2] = qadd(v[2], t);
        t = qcmul(v[7], TC3);
        v[7] = qsub(v[3], t, n1);
        v[3] = qadd(v[3], t);
    }
}

// ---------- scalar radix-8 (center only; unit twiddles fold) ----------
__device__ __forceinline__ void fwd8_s23(float2* v, float2 w2, float2 w4) {
    #pragma unroll
    for (int h = 0; h < 8; h += 4) {
        float2 u = csub(v[h + 0], v[h + 2]);
        v[h + 0] = cadd(v[h + 0], v[h + 2]);
        v[h + 2] = cmul(u, w2);
        u = csub(v[h + 1], v[h + 3]);
        v[h + 1] = cadd(v[h + 1], v[h + 3]);
        v[h + 3] = make_float2(u.x * w2.y + u.y * w2.x,
                               u.y * w2.y - u.x * w2.x);
    }
    #pragma unroll
    for (int h = 0; h < 8; h += 2) {
        const float2 u = csub(v[h], v[h + 1]);
        v[h] = cadd(v[h], v[h + 1]);
        v[h + 1] = cmul(u, w4);
    }
}
__device__ __forceinline__ void fwd8(float2* v, float2 w1, float2 w2, float2 w4) {
    const float2 wb = make_float2(S8 * (w1.x + w1.y), S8 * (w1.y - w1.x));
    const float2 wc = make_float2(w1.y, -w1.x);
    const float2 wd = make_float2(-S8 * (w1.x - w1.y), -S8 * (w1.y + w1.x));
    float2 s0 = cadd(v[0], v[4]), d0 = csub(v[0], v[4]);
    float2 s1 = cadd(v[1], v[5]), d1 = csub(v[1], v[5]);
    float2 s2 = cadd(v[2], v[6]), d2 = csub(v[2], v[6]);
    float2 s3 = cadd(v[3], v[7]), d3 = csub(v[3], v[7]);
    v[0] = s0; v[1] = s1; v[2] = s2; v[3] = s3;
    v[4] = cmul(d0, w1);
    v[5] = cmul(d1, wb);
    v[6] = cmul(d2, wc);
    v[7] = cmul(d3, wd);
    fwd8_s23(v, w2, w4);
}
__device__ __forceinline__ void inv8(float2* v, float2 w1, float2 w2, float2 w4) {
    #pragma unroll
    for (int h = 0; h < 8; h += 2) {
        const float2 t = cmulj(v[h + 1], w4);
        v[h + 1] = csub(v[h], t);
        v[h]     = cadd(v[h], t);
    }
    #pragma unroll
    for (int h = 0; h < 8; h += 4) {
        float2 t = cmulj(v[h + 2], w2);
        v[h + 2] = csub(v[h], t);
        v[h]     = cadd(v[h], t);
        t = make_float2(v[h + 3].x * w2.y - v[h + 3].y * w2.x,
                        v[h + 3].x * w2.x + v[h + 3].y * w2.y);
        v[h + 3] = csub(v[h + 1], t);
        v[h + 1] = cadd(v[h + 1], t);
    }
    {
        float2 t = cmulj(v[4], w1);
        v[4] = csub(v[0], t);
        v[0] = cadd(v[0], t);
        const float2 c1 = make_float2(S8 * (w1.x + w1.y), S8 * (w1.x - w1.y));
        t = cmul(v[5], c1);
        v[5] = csub(v[1], t);
        v[1] = cadd(v[1], t);
        t = make_float2(v[6].x * w1.y - v[6].y * w1.x,
                        v[6].x * w1.x + v[6].y * w1.y);
        v[6] = csub(v[2], t);
        v[2] = cadd(v[2], t);
        const float2 c3 = make_float2(-S8 * (w1.x - w1.y), S8 * (w1.y + w1.x));
        t = cmul(v[7], c3);
        v[7] = csub(v[3], t);
        v[3] = cadd(v[3], t);
    }
}

// Reduced midpair: given w2c = W_N^{2k} = W_M^k and hm = 0.5/M:
//   e = zk + conj-mix(zm) (=2E), o likewise (=2O)
//   E' = 0.5*hm*(e^2 + w2c*o^2),  O' = hm*(e*o)
__device__ __forceinline__ void midpair2(float2& zk, float2& zm, float2 w2c, float hm) {
    const float2 e = make_float2(zk.x + zm.x, zk.y - zm.y);
    const float2 o = make_float2(zk.y + zm.y, zm.x - zk.x);

    const float2 e2 = csq(e);
    const float2 o2 = csq(o);
    const float2 t  = cadd(e2, cmul(o2, w2c));

    const float hh = 0.5f * hm;
    const float Epr = hh * t.x, Epi = hh * t.y;
    const float2 eo = cmul(e, o);
    const float Opr = hm * eo.x, Opi = hm * eo.y;

    zk = make_float2(Epr - Opi, Epi + Opr);
    zm = make_float2(Epr + Opi, Opr - Epi);
}

__global__ void __launch_bounds__(NT, 1)
conv_self_rfft8a_kernel(const float* __restrict__ x, float* __restrict__ out) {
    q64* z = s_z;

    const int tid = threadIdx.x;
    const int b   = blockIdx.x;
    const q64 n1  = qpk(-1.0f, -1.0f);

    // twiddle bases, computed once, reused by mirror passes (1/D, 2/C, 3/B)
    const float2 w1a = twof(tid);               // pass1, passD
    const float2 w1b = twof((tid & 63) * 8);    // pass2, passC
    const float2 w1c = twof((tid & 7) * 64);    // pass3, passB

    // ---- fwd pass1: len=4096; inputs straight from gmem (k>=4 are pad zero)
    const q64* xb2 = (const q64*)(x + (size_t)b * SEQ_L);
    {
        q64 v[8];
        #pragma unroll
        for (int k = 0; k < 4; k++) v[k] = xb2[tid + k * 512];

        const float2 w2 = cmul(w1a, w1a);
        const float2 w4 = cmul(w2, w2);
        const qtw T1 = mk(w1a.x, w1a.y);
        const qtw TB = mk(S8 * (w1a.x + w1a.y), S8 * (w1a.y - w1a.x));
        const qtw TC = mk(w1a.y, -w1a.x);
        const qtw TD = mk(-S8 * (w1a.x - w1a.y), -S8 * (w1a.y + w1a.x));

        v[4] = qcmul(v[0], T1);
        v[5] = qcmul(v[1], TB);
        v[6] = qcmul(v[2], TC);
        v[7] = qcmul(v[3], TD);
        qfwd8_s23(v, w2, w4, n1);

        #pragma unroll
        for (int k = 0; k < 8; k++) z[IDX(tid + k * 512)] = v[k];
    }
    __syncthreads();

    // ---- fwd pass2: len=512 (64-thread groups), st=8
    {
        const int p = tid & 63;
        const int base = ((tid - p) << 3) + p;
        int ix[8];
        #pragma unroll
        for (int k = 0; k < 8; k++) ix[k] = IDX(base + k * 64);
        q64 v[8];
        #pragma unroll
        for (int k = 0; k < 8; k++) v[k] = z[ix[k]];
        const float2 w2 = cmul(w1b, w1b);
        const float2 w4 = cmul(w2, w2);
        qfwd8(v, w1b, w2, w4, n1);
        #pragma unroll
        for (int k = 0; k < 8; k++) z[ix[k]] = v[k];
    }
    BAR_PAIR(tid);

    // ---- fwd pass3: len=64 (warp-contained), st=64
    {
        const int p = tid & 7;
        const int base = ((tid - p) << 3) + p;
        int ix[8];
        #pragma unroll
        for (int k = 0; k < 8; k++) ix[k] = IDX(base + k * 8);
        q64 v[8];
        #pragma unroll
        for (int k = 0; k < 8; k++) v[k] = z[ix[k]];
        const float2 w2 = cmul(w1c, w1c);
        const float2 w4 = cmul(w2, w2);
        qfwd8(v, w1c, w2, w4, n1);
        #pragma unroll
        for (int k = 0; k < 8; k++) z[ix[k]] = v[k];
    }
    __syncthreads();   // center reads octets across warps

    // ---- Register-fused center: fwd pass4 + reduced middle + inv passA on
    //      mirrored octet pairs. W^2 per bin = W_M^{k_base} * E8^{brev3(r)}.
    if (tid < 256) {
        int oa, oc;
        if (tid == 0) { oa = 0; oc = 1; }
        else {
            const int msbu = 1 << (31 - __clz(tid));
            const int O = msbu << 1;
            oa = O + (tid - msbu);
            oc = 3 * O - 1 - oa;
        }

        float2 a[8], c[8];
        {
            const float4* pa = (const float4*)&z[IDX(8 * oa)];
            const float4* pc = (const float4*)&z[IDX(8 * oc)];
            #pragma unroll
            for (int i = 0; i < 4; i++) {
                float4 va = pa[i], vc = pc[i];
                a[2 * i]     = make_float2(va.x, va.y);
                a[2 * i + 1] = make_float2(va.z, va.w);
                c[2 * i]     = make_float2(vc.x, vc.y);
                c[2 * i + 1] = make_float2(vc.z, vc.w);
            }
        }

        const float2 one = make_float2(1.f, 0.f);
        fwd8(a, one, one, one);
        fwd8(c, one, one, one);

        const float hm = 0.5f / (float)FFT_M;
        if (tid == 0) {
            {   // DC/Nyquist and self-paired k=M/2 bins
                const float P = a[0].x + a[0].y, Q = a[0].x - a[0].y;
                const float P2 = P * P, Q2 = Q * Q;
                a[0] = make_float2(hm * (P2 + Q2), hm * (P2 - Q2));
                a[1] = make_float2(2.0f * hm * (a[1].x * a[1].x - a[1].y * a[1].y),
                                   2.0f * hm * (2.0f * a[1].x * a[1].y));
            }
            // exact W^2 = W_M^k constants: k = 1024,512,2560,256,2304,1280,3328
            midpair2(a[2], a[3], make_float2(0.f, -1.f), hm);
            midpair2(a[4], a[7], make_float2(S8, -S8), hm);
            midpair2(a[5], a[6], make_float2(-S8, S8), hm);
            midpair2(c[0], c[7], make_float2(C16, -S16), hm);
            midpair2(c[1], c[6], make_float2(-C16, S16), hm);
            midpair2(c[2], c[5], make_float2(-S16, -C16), hm);
            midpair2(c[3], c[4], make_float2(S16, C16), hm);
        } else {
            const int kb0 = 8 * oa;
            const int k_base = __brev((unsigned)kb0) >> 20;
            const float2 w2b = twof(k_base);     // W_M^{k_base}
            // E8^{brev3(r)} rotations of w2b, r = 0..7
            const float2 W0 = w2b;                                            // j=0
            const float2 W1 = make_float2(-w2b.x, -w2b.y);                    // j=4
            const float2 W2 = make_float2(w2b.y, -w2b.x);                     // j=2
            const float2 W3 = make_float2(-w2b.y, w2b.x);                     // j=6
            const float2 W4 = make_float2(S8 * (w2b.x + w2b.y),
                                          S8 * (w2b.y - w2b.x));              // j=1
            const float2 W5 = make_float2(-W4.x, -W4.y);                      // j=5
            const float2 W6 = make_float2(S8 * (w2b.y - w2b.x),
                                          -S8 * (w2b.x + w2b.y));             // j=3
            const float2 W7 = make_float2(-W6.x, -W6.y);                      // j=7
            midpair2(a[0], c[7], W0, hm);
            midpair2(a[1], c[6], W1, hm);
            midpair2(a[2], c[5], W2, hm);
            midpair2(a[3], c[4], W3, hm);
            midpair2(a[4], c[3], W4, hm);
            midpair2(a[5], c[2], W5, hm);
            midpair2(a[6], c[1], W6, hm);
            midpair2(a[7], c[0], W7, hm);
        }

        inv8(a, one, one, one);
        inv8(c, one, one, one);

        {
            float4* pa = (float4*)&z[IDX(8 * oa)];
            float4* pc = (float4*)&z[IDX(8 * oc)];
            #pragma unroll
            for (int i = 0; i < 4; i++) {
                pa[i] = make_float4(a[2 * i].x, a[2 * i].y,
                                    a[2 * i + 1].x, a[2 * i + 1].y);
                pc[i] = make_float4(c[2 * i].x, c[2 * i].y,
                                    c[2 * i + 1].x, c[2 * i + 1].y);
            }
        }
    }
    __syncthreads();

    // ---- inv passB: lenBig=64 (warp-contained), st=64
    {
        const int p = tid & 7;
        const int base = ((tid - p) << 3) + p;
        int ix[8];
        #pragma unroll
        for (int k = 0; k < 8; k++) ix[k] = IDX(base + k * 8);
        q64 v[8];
        #pragma unroll
        for (int k = 0; k < 8; k++) v[k] = z[ix[k]];
        const float2 w2 = cmul(w1c, w1c);
        const float2 w4 = cmul(w2, w2);
        qinv8(v, w1c, w2, w4, n1);
        #pragma unroll
        for (int k = 0; k < 8; k++) z[ix[k]] = v[k];
    }
    BAR_PAIR(tid);

    // ---- inv passC: lenBig=512 (64-thread groups), st=8
    {
        const int p = tid & 63;
        const int base = ((tid - p) << 3) + p;
        int ix[8];
        #pragma unroll
        for (int k = 0; k < 8; k++) ix[k] = IDX(base + k * 64);
        q64 v[8];
        #pragma unroll
        for (int k = 0; k < 8; k++) v[k] = z[ix[k]];
        const float2 w2 = cmul(w1b, w1b);
        const float2 w4 = cmul(w2, w2);
        qinv8(v, w1b, w2, w4, n1);
        #pragma unroll
        for (int k = 0; k < 8; k++) z[ix[k]] = v[k];
    }
    __syncthreads();

    // ---- inv passD: lenBig=4096, thread-local slots (tid + 512k)
    q64 v[8];
    {
        #pragma unroll
        for (int k = 0; k < 8; k++) v[k] = z[IDX(tid + k * 512)];
        const float2 w2 = cmul(w1a, w1a);
        const float2 w4 = cmul(w2, w2);
        qinv8(v, w1a, w2, w4, n1);
    }
    // no barrier: store reads this thread's registers

    // ---- Store (already scaled). Only tid=511,k=7 hits the 8191 edge.
    float* ob = out + (size_t)b * OUT_L;
    #pragma unroll
    for (int k = 0; k < 7; k++) {
        const int m = tid + k * 512;
        const float2 f = qun(v[k]);
        ob[2 * m]     = f.x;
        ob[2 * m + 1] = f.y;
    }
    {
        const int m = tid + 7 * 512;
        const float2 f = qun(v[7]);
        ob[2 * m] = f.x;
        if (tid != 511) ob[2 * m + 1] = f.y;
    }
}

extern "C" void kernel_launch(void* const* d_in, const int* in_sizes, int n_in,
                              void* d_out, int out_size) {
    (void)in_sizes; (void)n_in; (void)out_size;
    const float* x = (const float*)d_in[0];
    float* out = (float*)d_out;

    const int smem_bytes = RE_SZ * (int)sizeof(q64);  // 36 KB
    cudaFuncSetAttribute(conv_self_rfft8a_kernel,
                         cudaFuncAttributeMaxDynamicSharedMemorySize, smem_bytes);

    conv_self_rfft8a_kernel<<<128, NT, smem_bytes>>>(x, out);
}

// round 13
// speedup vs baseline: 1.2620x; 1.2620x over previous
#include <cuda_runtime.h>
#include <math.h>

// Self-convolution via real-packed shared-memory FFT: radix-8 fused passes,
// NT=512, packed f32x2 everywhere (including the register-fused center),
// scoped sync, table-free twiddles, zero-pad-aware pass1 (gmem->regs),
// reduced middle (O' twiddle cancels), hoisted smem index arrays.

#define SEQ_L   4096
#define OUT_L   (2 * SEQ_L - 1)     // 8191
#define FFT_M   4096
#define NT      512

#define IDX(a)  ((a) + (((a) >> 4) << 1))       // pad 2 slots per 16
#define RE_SZ   (FFT_M + ((FFT_M >> 4) << 1))   // 4608 complex slots (36 KB)
#define S8      0.70710678118654752440f
#define C16     0.92387953251128675613f
#define S16     0.38268343236508977173f
#define W_ANG   (-6.28318530717958647692f / (float)FFT_M)

#define BAR_PAIR(tid) asm volatile("bar.sync %0, 64;" :: "r"(1 + ((tid) >> 6)) : "memory")

typedef unsigned long long q64;   // packed (float lo, float hi) complex

// ---------- packed f32x2 primitives ----------
__device__ __forceinline__ q64 qpk(float x, float y) {
    q64 r; asm("mov.b64 %0,{%1,%2};" : "=l"(r) : "f"(x), "f"(y)); return r;
}
__device__ __forceinline__ float2 qun(q64 a) {
    float2 f; asm("mov.b64 {%0,%1},%2;" : "=f"(f.x), "=f"(f.y) : "l"(a)); return f;
}
__device__ __forceinline__ q64 qswp(q64 a) {
    q64 r;
    asm("{\n\t.reg .b32 lo,hi;\n\tmov.b64 {lo,hi},%1;\n\tmov.b64 %0,{hi,lo};\n\t}"
        : "=l"(r) : "l"(a));
    return r;
}
__device__ __forceinline__ q64 qadd(q64 a, q64 b) {
    q64 r; asm("add.rn.f32x2 %0,%1,%2;" : "=l"(r) : "l"(a), "l"(b)); return r;
}
__device__ __forceinline__ q64 qmul(q64 a, q64 b) {
    q64 r; asm("mul.rn.f32x2 %0,%1,%2;" : "=l"(r) : "l"(a), "l"(b)); return r;
}
__device__ __forceinline__ q64 qfma(q64 a, q64 b, q64 c) {
    q64 r; asm("fma.rn.f32x2 %0,%1,%2,%3;" : "=l"(r) : "l"(a), "l"(b), "l"(c)); return r;
}
__device__ __forceinline__ q64 qsub(q64 a, q64 b, q64 n1) { return qfma(b, n1, a); }

struct qtw { q64 xx, sy; };
__device__ __forceinline__ qtw mk(float p, float q) {
    qtw t; t.xx = qpk(p, p); t.sy = qpk(-q, q); return t;
}
__device__ __forceinline__ q64 qcmul(q64 a, qtw t) {
    return qfma(qswp(a), t.sy, qmul(a, t.xx));
}

// ---------- scalar complex helpers (twiddle generation / midpair core) ----------
__device__ __forceinline__ float2 cmul(float2 a, float2 w) {
    return make_float2(a.x * w.x - a.y * w.y, a.x * w.y + a.y * w.x);
}
__device__ __forceinline__ float2 cadd(float2 a, float2 b) {
    return make_float2(a.x + b.x, a.y + b.y);
}
__device__ __forceinline__ float2 csq(float2 a) {
    return make_float2(a.x * a.x - a.y * a.y, 2.0f * a.x * a.y);
}
__device__ __forceinline__ float2 twof(int t) {   // exp(i * W_ANG * t)
    float2 w;
    __sincosf(W_ANG * (float)t, &w.y, &w.x);
    return w;
}

extern __shared__ q64 s_z[];

// ---------- packed radix-8 (general twiddles) ----------
__device__ __forceinline__ void qfwd8_s23(q64 v[8], float2 w2, float2 w4, q64 n1) {
    const qtw T2  = mk(w2.x, w2.y);
    const qtw T2N = mk(w2.y, -w2.x);
    #pragma unroll
    for (int h = 0; h < 8; h += 4) {
        q64 u = qsub(v[h + 0], v[h + 2], n1);
        v[h + 0] = qadd(v[h + 0], v[h + 2]);
        v[h + 2] = qcmul(u, T2);
        u = qsub(v[h + 1], v[h + 3], n1);
        v[h + 1] = qadd(v[h + 1], v[h + 3]);
        v[h + 3] = qcmul(u, T2N);
    }
    const qtw T4 = mk(w4.x, w4.y);
    #pragma unroll
    for (int h = 0; h < 8; h += 2) {
        const q64 u = qsub(v[h], v[h + 1], n1);
        v[h] = qadd(v[h], v[h + 1]);
        v[h + 1] = qcmul(u, T4);
    }
}

__device__ __forceinline__ void qfwd8(q64 v[8], float2 w1, float2 w2, float2 w4, q64 n1) {
    const qtw T1 = mk(w1.x, w1.y);
    const qtw TB = mk(S8 * (w1.x + w1.y), S8 * (w1.y - w1.x));
    const qtw TC = mk(w1.y, -w1.x);
    const qtw TD = mk(-S8 * (w1.x - w1.y), -S8 * (w1.y + w1.x));

    q64 d0 = qsub(v[0], v[4], n1), d1 = qsub(v[1], v[5], n1);
    q64 d2 = qsub(v[2], v[6], n1), d3 = qsub(v[3], v[7], n1);
    v[0] = qadd(v[0], v[4]);
    v[1] = qadd(v[1], v[5]);
    v[2] = qadd(v[2], v[6]);
    v[3] = qadd(v[3], v[7]);
    v[4] = qcmul(d0, T1);
    v[5] = qcmul(d1, TB);
    v[6] = qcmul(d2, TC);
    v[7] = qcmul(d3, TD);

    qfwd8_s23(v, w2, w4, n1);
}

__device__ __forceinline__ void qinv8(q64 v[8], float2 w1, float2 w2, float2 w4, q64 n1) {
    const qtw T4C = mk(w4.x, -w4.y);
    #pragma unroll
    for (int h = 0; h < 8; h += 2) {
        const q64 t = qcmul(v[h + 1], T4C);
        v[h + 1] = qsub(v[h], t, n1);
        v[h]     = qadd(v[h], t);
    }
    const qtw T2C = mk(w2.x, -w2.y);
    const qtw T2I = mk(w2.y, w2.x);
    #pragma unroll
    for (int h = 0; h < 8; h += 4) {
        q64 t = qcmul(v[h + 2], T2C);
        v[h + 2] = qsub(v[h], t, n1);
        v[h]     = qadd(v[h], t);
        t = qcmul(v[h + 3], T2I);
        v[h + 3] = qsub(v[h + 1], t, n1);
        v[h + 1] = qadd(v[h + 1], t);
    }
    {
        const qtw T1C = mk(w1.x, -w1.y);
        const qtw TC1 = mk(S8 * (w1.x + w1.y), S8 * (w1.x - w1.y));
        const qtw TC2 = mk(w1.y, w1.x);
        const qtw TC3 = mk(-S8 * (w1.x - w1.y), S8 * (w1.y + w1.x));

        q64 t = qcmul(v[4], T1C);
        v[4] = qsub(v[0], t, n1);
        v[0] = qadd(v[0], t);
        t = qcmul(v[5], TC1);
        v[5] = qsub(v[1], t, n1);
        v[1] = qadd(v[1], t);
        t = qcmul(v[6], TC2);
        v[6] = qsub(v[2], t, n1);
        v[2] = qadd(v[2], t);
        t = qcmul(v[7], TC3);
        v[7] = qsub(v[3], t, n1);
        v[3] = qadd(v[3], t);
    }
}

// ---------- packed radix-8, UNIT twiddles (center) ----------
__device__ __forceinline__ void ufwd8(q64 v[8], q64 n1, q64 p1m1) {
    const qtw TC8  = mk(S8, -S8);     // * c8
    const qtw TMC8 = mk(-S8, -S8);    // * (-i*c8)
    q64 s0 = qadd(v[0], v[4]), d0 = qsub(v[0], v[4], n1);
    q64 s1 = qadd(v[1], v[5]), d1 = qsub(v[1], v[5], n1);
    q64 s2 = qadd(v[2], v[6]), d2 = qsub(v[2], v[6], n1);
    q64 s3 = qadd(v[3], v[7]), d3 = qsub(v[3], v[7], n1);
    v[0] = s0; v[1] = s1; v[2] = s2; v[3] = s3;
    v[4] = d0;
    v[5] = qcmul(d1, TC8);
    v[6] = qmul(qswp(d2), p1m1);      // * -i
    v[7] = qcmul(d3, TMC8);

    #pragma unroll
    for (int h = 0; h < 8; h += 4) {
        q64 u = qsub(v[h + 0], v[h + 2], n1);
        v[h + 0] = qadd(v[h + 0], v[h + 2]);
        v[h + 2] = u;
        u = qsub(v[h + 1], v[h + 3], n1);
        v[h + 1] = qadd(v[h + 1], v[h + 3]);
        v[h + 3] = qmul(qswp(u), p1m1);   // * -i
    }
    #pragma unroll
    for (int h = 0; h < 8; h += 2) {
        const q64 u = qsub(v[h], v[h + 1], n1);
        v[h] = qadd(v[h], v[h + 1]);
        v[h + 1] = u;
    }
}

__device__ __forceinline__ void uinv8(q64 v[8], q64 n1, q64 m1p1) {
    #pragma unroll
    for (int h = 0; h < 8; h += 2) {
        const q64 t = v[h + 1];
        v[h + 1] = qsub(v[h], t, n1);
        v[h]     = qadd(v[h], t);
    }
    #pragma unroll
    for (int h = 0; h < 8; h += 4) {
        q64 t = v[h + 2];
        v[h + 2] = qsub(v[h], t, n1);
        v[h]     = qadd(v[h], t);
        t = qmul(qswp(v[h + 3]), m1p1);   // * +i
        v[h + 3] = qsub(v[h + 1], t, n1);
        v[h + 1] = qadd(v[h + 1], t);
    }
    {
        const qtw TC1 = mk(S8, S8);       // conj path k=1
        const qtw TC3 = mk(-S8, S8);      // conj path k=3
        q64 t = v[4];
        v[4] = qsub(v[0], t, n1);
        v[0] = qadd(v[0], t);
        t = qcmul(v[5], TC1);
        v[5] = qsub(v[1], t, n1);
        v[1] = qadd(v[1], t);
        t = qmul(qswp(v[6]), m1p1);       // * +i
        v[6] = qsub(v[2], t, n1);
        v[2] = qadd(v[2], t);
        t = qcmul(v[7], TC3);
        v[7] = qsub(v[3], t, n1);
        v[3] = qadd(v[3], t);
    }
}

// Reduced midpair, packed ends: E' = 0.5*hm*(e^2 + w2c*o^2), O' = hm*e*o.
__device__ __forceinline__ void midpair2q(q64& zk, q64& zm, float2 w2c, float hm,
                                          q64 p1m1, q64 m1p1) {
    const q64 e = qfma(zm, p1m1, zk);                     // (zk.x+zm.x, zk.y-zm.y)
    const q64 o = qfma(qswp(zk), p1m1, qswp(zm));         // (zk.y+zm.y, zm.x-zk.x)

    const float2 ef = qun(e), of = qun(o);
    const float2 t  = cadd(csq(ef), cmul(csq(of), w2c));
    const float hh  = 0.5f * hm;
    const float2 eo = cmul(ef, of);

    const q64 EP = qpk(hh * t.x, hh * t.y);
    const q64 OP = qpk(hm * eo.x, hm * eo.y);

    zk = qfma(qswp(OP), m1p1, EP);                        // (Epr-Opi, Epi+Opr)
    zm = qfma(EP, p1m1, qswp(OP));                        // (Epr+Opi, Opr-Epi)
}

__global__ void __launch_bounds__(NT, 1)
conv_self_rfft8z_kernel(const float* __restrict__ x, float* __restrict__ out) {
    q64* z = s_z;

    const int tid = threadIdx.x;
    const int b   = blockIdx.x;
    const q64 n1   = qpk(-1.0f, -1.0f);
    const q64 p1m1 = qpk(1.0f, -1.0f);
    const q64 m1p1 = qpk(-1.0f, 1.0f);

    // ---- gmem loads FIRST (overlap DRAM latency with MUFU below) ----
    const q64* xb2 = (const q64*)(x + (size_t)b * SEQ_L);
    q64 g0 = xb2[tid], g1 = xb2[tid + 512], g2 = xb2[tid + 1024], g3 = xb2[tid + 1536];

    // twiddle bases, computed once, reused by mirror passes (1/D, 2/C, 3/B)
    const float2 w1a = twof(tid);
    const float2 w1b = twof((tid & 63) * 8);
    const float2 w1c = twof((tid & 7) * 64);

    // hoisted smem index arrays (shared by fwd/inv mirror passes)
    int ixb[8], ixc[8];
    {
        const int p2 = tid & 63;
        const int b2 = ((tid - p2) << 3) + p2;
        const int p3 = tid & 7;
        const int b3 = ((tid - p3) << 3) + p3;
        #pragma unroll
        for (int k = 0; k < 8; k++) {
            ixb[k] = IDX(b2 + k * 64);
            ixc[k] = IDX(b3 + k * 8);
        }
    }

    // ---- fwd pass1: len=4096; inputs in regs; upper half structural zero
    {
        q64 v[8];
        v[0] = g0; v[1] = g1; v[2] = g2; v[3] = g3;

        const float2 w2 = cmul(w1a, w1a);
        const float2 w4 = cmul(w2, w2);
        const qtw T1 = mk(w1a.x, w1a.y);
        const qtw TB = mk(S8 * (w1a.x + w1a.y), S8 * (w1a.y - w1a.x));
        const qtw TC = mk(w1a.y, -w1a.x);
        const qtw TD = mk(-S8 * (w1a.x - w1a.y), -S8 * (w1a.y + w1a.x));

        v[4] = qcmul(v[0], T1);
        v[5] = qcmul(v[1], TB);
        v[6] = qcmul(v[2], TC);
        v[7] = qcmul(v[3], TD);
        qfwd8_s23(v, w2, w4, n1);

        #pragma unroll
        for (int k = 0; k < 8; k++) z[IDX(tid + k * 512)] = v[k];
    }
    __syncthreads();

    // ---- fwd pass2: len=512 (64-thread groups)
    {
        q64 v[8];
        #pragma unroll
        for (int k = 0; k < 8; k++) v[k] = z[ixb[k]];
        const float2 w2 = cmul(w1b, w1b);
        const float2 w4 = cmul(w2, w2);
        qfwd8(v, w1b, w2, w4, n1);
        #pragma unroll
        for (int k = 0; k < 8; k++) z[ixb[k]] = v[k];
    }
    BAR_PAIR(tid);

    // ---- fwd pass3: len=64 (warp-contained)
    {
        q64 v[8];
        #pragma unroll
        for (int k = 0; k < 8; k++) v[k] = z[ixc[k]];
        const float2 w2 = cmul(w1c, w1c);
        const float2 w4 = cmul(w2, w2);
        qfwd8(v, w1c, w2, w4, n1);
        #pragma unroll
        for (int k = 0; k < 8; k++) z[ixc[k]] = v[k];
    }
    __syncthreads();

    // ---- Register-fused center (packed): fwd pass4 + reduced middle + inv passA
    if (tid < 256) {
        int oa, oc;
        if (tid == 0) { oa = 0; oc = 1; }
        else {
            const int msbu = 1 << (31 - __clz(tid));
            const int O = msbu << 1;
            oa = O + (tid - msbu);
            oc = 3 * O - 1 - oa;
        }

        q64 a[8], c[8];
        {
            const float4* pa = (const float4*)&z[IDX(8 * oa)];
            const float4* pc = (const float4*)&z[IDX(8 * oc)];
            #pragma unroll
            for (int i = 0; i < 4; i++) {
                const float4 va = pa[i], vc = pc[i];
                a[2 * i]     = qpk(va.x, va.y);
                a[2 * i + 1] = qpk(va.z, va.w);
                c[2 * i]     = qpk(vc.x, vc.y);
                c[2 * i + 1] = qpk(vc.z, vc.w);
            }
        }

        ufwd8(a, n1, p1m1);
        ufwd8(c, n1, p1m1);

        const float hm = 0.5f / (float)FFT_M;
        if (tid == 0) {
            {   // DC/Nyquist and self-paired k=M/2 bins
                const float2 z0 = qun(a[0]);
                const float P = z0.x + z0.y, Q = z0.x - z0.y;
                a[0] = qpk(hm * (P * P + Q * Q), hm * (P * P - Q * Q));
                const float2 z1 = qun(a[1]);
                a[1] = qpk(2.0f * hm * (z1.x * z1.x - z1.y * z1.y),
                           4.0f * hm * (z1.x * z1.y));
            }
            midpair2q(a[2], a[3], make_float2(0.f, -1.f), hm, p1m1, m1p1);
            midpair2q(a[4], a[7], make_float2(S8, -S8), hm, p1m1, m1p1);
            midpair2q(a[5], a[6], make_float2(-S8, S8), hm, p1m1, m1p1);
            midpair2q(c[0], c[7], make_float2(C16, -S16), hm, p1m1, m1p1);
            midpair2q(c[1], c[6], make_float2(-C16, S16), hm, p1m1, m1p1);
            midpair2q(c[2], c[5], make_float2(-S16, -C16), hm, p1m1, m1p1);
            midpair2q(c[3], c[4], make_float2(S16, C16), hm, p1m1, m1p1);
        } else {
            const int k_base = __brev((unsigned)(8 * oa)) >> 20;
            const float2 w2b = twof(k_base);     // W_M^{k_base}
            const float2 W0 = w2b;
            const float2 W1 = make_float2(-w2b.x, -w2b.y);
            const float2 W2 = make_float2(w2b.y, -w2b.x);
            const float2 W3 = make_float2(-w2b.y, w2b.x);
            const float2 W4 = make_float2(S8 * (w2b.x + w2b.y), S8 * (w2b.y - w2b.x));
            const float2 W5 = make_float2(-W4.x, -W4.y);
            const float2 W6 = make_float2(S8 * (w2b.y - w2b.x), -S8 * (w2b.x + w2b.y));
            const float2 W7 = make_float2(-W6.x, -W6.y);
            midpair2q(a[0], c[7], W0, hm, p1m1, m1p1);
            midpair2q(a[1], c[6], W1, hm, p1m1, m1p1);
            midpair2q(a[2], c[5], W2, hm, p1m1, m1p1);
            midpair2q(a[3], c[4], W3, hm, p1m1, m1p1);
            midpair2q(a[4], c[3], W4, hm, p1m1, m1p1);
            midpair2q(a[5], c[2], W5, hm, p1m1, m1p1);
            midpair2q(a[6], c[1], W6, hm, p1m1, m1p1);
            midpair2q(a[7], c[0], W7, hm, p1m1, m1p1);
        }

        uinv8(a, n1, m1p1);
        uinv8(c, n1, m1p1);

        {
            float4* pa = (float4*)&z[IDX(8 * oa)];
            float4* pc = (float4*)&z[IDX(8 * oc)];
            #pragma unroll
            for (int i = 0; i < 4; i++) {
                const float2 a0 = qun(a[2 * i]), a1 = qun(a[2 * i + 1]);
                const float2 c0 = qun(c[2 * i]), c1 = qun(c[2 * i + 1]);
                pa[i] = make_float4(a0.x, a0.y, a1.x, a1.y);
                pc[i] = make_float4(c0.x, c0.y, c1.x, c1.y);
            }
        }
    }
    __syncthreads();

    // ---- inv passB: lenBig=64 (warp-contained)
    {
        q64 v[8];
        #pragma unroll
        for (int k = 0; k < 8; k++) v[k] = z[ixc[k]];
        const float2 w2 = cmul(w1c, w1c);
        const float2 w4 = cmul(w2, w2);
        qinv8(v, w1c, w2, w4, n1);
        #pragma unroll
        for (int k = 0; k < 8; k++) z[ixc[k]] = v[k];
    }
    BAR_PAIR(tid);

    // ---- inv passC: lenBig=512 (64-thread groups)
    {
        q64 v[8];
        #pragma unroll
        for (int k = 0; k < 8; k++) v[k] = z[ixb[k]];
        const float2 w2 = cmul(w1b, w1b);
        const float2 w4 = cmul(w2, w2);
        qinv8(v, w1b, w2, w4, n1);
        #pragma unroll
        for (int k = 0; k < 8; k++) z[ixb[k]] = v[k];
    }
    __syncthreads();

    // ---- inv passD: lenBig=4096, thread-local slots (tid + 512k)
    q64 v[8];
    {
        #pragma unroll
        for (int k = 0; k < 8; k++) v[k] = z[IDX(tid + k * 512)];
        const float2 w2 = cmul(w1a, w1a);
        const float2 w4 = cmul(w2, w2);
        qinv8(v, w1a, w2, w4, n1);
    }
    // no barrier: store reads this thread's registers

    // ---- Store (already scaled). Only tid=511,k=7 hits the 8191 edge.
    float* ob = out + (size_t)b * OUT_L;
    #pragma unroll
    for (int k = 0; k < 7; k++) {
        const int m = tid + k * 512;
        const float2 f = qun(v[k]);
        ob[2 * m]     = f.x;
        ob[2 * m + 1] = f.y;
    }
    {
        const int m = tid + 7 * 512;
        const float2 f = qun(v[7]);
        ob[2 * m] = f.x;
        if (tid != 511) ob[2 * m + 1] = f.y;
    }
}

extern "C" void kernel_launch(void* const* d_in, const int* in_sizes, int n_in,
                              void* d_out, int out_size) {
    (void)in_sizes; (void)n_in; (void)out_size;
    const float* x = (const float*)d_in[0];
    float* out = (float*)d_out;

    const int smem_bytes = RE_SZ * (int)sizeof(q64);  // 36 KB
    cudaFuncSetAttribute(conv_self_rfft8z_kernel,
                         cudaFuncAttributeMaxDynamicSharedMemorySize, smem_bytes);

    conv_self_rfft8z_kernel<<<128, NT, smem_bytes>>>(x, out);
}